// round 6
// baseline (speedup 1.0000x reference)
#include <cuda_runtime.h>

#define TB 256
#define WLD 20

__device__ float g_seq[131072*192];
__device__ float g_qkv[131072*576];
__device__ float g_ctx[131072*192];
__device__ float g_x  [131072*192];
__device__ float g_h  [131072*384];
__device__ float g_z  [65536*192];
__device__ float g_h1 [65536*192];

__device__ __forceinline__ unsigned f2tf(float x){unsigned r;asm("cvt.rna.tf32.f32 %0,%1;":"=r"(r):"f"(x));return r;}
__device__ __forceinline__ void mma8(float* d,unsigned a0,unsigned a1,unsigned a2,unsigned a3,unsigned b0,unsigned b1){
  asm volatile("mma.sync.aligned.m16n8k8.row.col.f32.tf32.tf32.f32 {%0,%1,%2,%3},{%4,%5,%6,%7},{%8,%9},{%0,%1,%2,%3};"
    :"+f"(d[0]),"+f"(d[1]),"+f"(d[2]),"+f"(d[3]):"r"(a0),"r"(a1),"r"(a2),"r"(a3),"r"(b0),"r"(b1));}
__device__ __forceinline__ void cpa16(float* dst,const float* src){
  unsigned d=(unsigned)__cvta_generic_to_shared(dst);
  asm volatile("cp.async.cg.shared.global [%0],[%1],16;"::"r"(d),"l"(src));}

template<int KTOT>
__device__ __forceinline__ void load_tile(float* Xs,int xld,const float* X,int xstride,int row0,int tid){
  for(int idx=tid; idx<64*(KTOT/4); idx+=TB){
    int r=idx/(KTOT/4), c=idx%(KTOT/4);
    *(float4*)(Xs+r*xld+c*4)=*(const float4*)(X+(long)(row0+r)*xstride+c*4);
  }
}

// acc[NT][4] += Xs[64,KTOT] @ W[N,KTOT]^T  (3-term tf32 split, warps 4x2)
template<int KTOT,int NT>
__device__ __forceinline__ void gemm_tile(float (*acc)[4],const float* Xs,int xld,
    const float* __restrict__ Wg,float* Wb,int tid){
  constexpr int N=NT*16, NC=KTOT/16;
  int lane=tid&31,warp=tid>>5,wm=warp&3,wn=warp>>2,gid=lane>>2,t4=lane&3;
  #pragma unroll
  for(int i=0;i<NT;i++){acc[i][0]=0.f;acc[i][1]=0.f;acc[i][2]=0.f;acc[i][3]=0.f;}
  for(int idx=tid; idx<N*4; idx+=TB){int r=idx>>2,s=idx&3; cpa16(Wb+r*WLD+s*4,Wg+r*KTOT+s*4);}
  asm volatile("cp.async.commit_group;");
  for(int c=0;c<NC;c++){
    const float* cur=Wb+(c&1)*(N*WLD);
    float* nxt=Wb+((c+1)&1)*(N*WLD);
    if(c+1<NC){
      for(int idx=tid; idx<N*4; idx+=TB){int r=idx>>2,s=idx&3; cpa16(nxt+r*WLD+s*4,Wg+r*KTOT+(c+1)*16+s*4);}
      asm volatile("cp.async.commit_group;");
      asm volatile("cp.async.wait_group 1;");
    } else { asm volatile("cp.async.wait_group 0;"); }
    __syncthreads();
    #pragma unroll
    for(int ks=0;ks<2;ks++){
      const float* xr=Xs+(wm*16+gid)*xld+c*16+ks*8;
      float a0=xr[t4],a1=xr[8*xld+t4],a2=xr[t4+4],a3=xr[8*xld+t4+4];
      unsigned ah0=f2tf(a0),ah1=f2tf(a1),ah2=f2tf(a2),ah3=f2tf(a3);
      unsigned al0=f2tf(a0-__uint_as_float(ah0)),al1=f2tf(a1-__uint_as_float(ah1));
      unsigned al2=f2tf(a2-__uint_as_float(ah2)),al3=f2tf(a3-__uint_as_float(ah3));
      #pragma unroll
      for(int nt=0;nt<NT;nt++){
        const float* wr=cur+(wn*(NT*8)+nt*8+gid)*WLD+ks*8;
        float b0=wr[t4],b1=wr[t4+4];
        unsigned bh0=f2tf(b0),bh1=f2tf(b1);
        unsigned bl0=f2tf(b0-__uint_as_float(bh0)),bl1=f2tf(b1-__uint_as_float(bh1));
        mma8(acc[nt],ah0,ah1,ah2,ah3,bh0,bh1);
        mma8(acc[nt],al0,al1,al2,al3,bh0,bh1);
        mma8(acc[nt],ah0,ah1,ah2,ah3,bl0,bl1);
      }
    }
    __syncthreads();
  }
}

// generic: Y[row, n0+n] = (relu?)(X@W^T + b), N chunks of NT*16 via blockIdx.y
template<int KTOT,int NT>
__global__ __launch_bounds__(TB,1) void k_gemm(const float* __restrict__ X,int xstride,
    float* __restrict__ Y,int ystride,const float* __restrict__ W,const float* __restrict__ bias,int relu){
  extern __shared__ float sm[];
  constexpr int XLD=KTOT+4;
  float* Xs=sm; float* Wb=sm+64*XLD;
  int tid=threadIdx.x,row0=blockIdx.x*64,n0=blockIdx.y*(NT*16);
  load_tile<KTOT>(Xs,XLD,X,xstride,row0,tid);
  __syncthreads();
  float acc[NT][4];
  gemm_tile<KTOT,NT>(acc,Xs,XLD,W+(long)n0*KTOT,Wb,tid);
  int lane=tid&31,warp=tid>>5,wm=warp&3,wn=warp>>2,gid=lane>>2,t4=lane&3;
  #pragma unroll
  for(int nt=0;nt<NT;nt++){
    int n=wn*(NT*8)+nt*8+2*t4;
    #pragma unroll
    for(int e=0;e<4;e++){
      int m=wm*16+gid+(e>>1)*8, nn=n+(e&1);
      float v=acc[nt][e]+bias[n0+nn];
      if(relu) v=fmaxf(v,0.f);
      Y[(long)(row0+m)*ystride+n0+nn]=v;
    }
  }
}

// GEMM(192 out) + residual + LayerNorm; POOL: also mean over token pairs -> Out[B,192]
template<int KTOT,bool POOL>
__global__ __launch_bounds__(TB,1) void k_ln(const float* __restrict__ X,
    const float* __restrict__ res,const float* __restrict__ W,const float* __restrict__ bias,
    const float* __restrict__ lg,const float* __restrict__ lb,float* __restrict__ Out){
  extern __shared__ float sm[];
  constexpr int XLD=KTOT+4;
  float* Xs=sm; float* Wb=Xs+64*XLD; float* Ys=Wb+2*192*WLD;
  int tid=threadIdx.x,row0=blockIdx.x*64;
  load_tile<KTOT>(Xs,XLD,X,KTOT,row0,tid);
  __syncthreads();
  float acc[12][4];
  gemm_tile<KTOT,12>(acc,Xs,XLD,W,Wb,tid);
  for(int idx=tid; idx<64*48; idx+=TB){int r=idx/48,c=idx%48;
    *(float4*)(Xs+r*196+c*4)=*(const float4*)(res+(long)(row0+r)*192+c*4);}
  __syncthreads();
  int lane=tid&31,warp=tid>>5,wm=warp&3,wn=warp>>2,gid=lane>>2,t4=lane&3;
  #pragma unroll
  for(int nt=0;nt<12;nt++){
    int n=wn*96+nt*8+2*t4;
    #pragma unroll
    for(int e=0;e<4;e++){
      int m=wm*16+gid+(e>>1)*8,nn=n+(e&1);
      Ys[m*196+nn]=acc[nt][e]+bias[nn]+Xs[m*196+nn];
    }
  }
  __syncthreads();
  for(int r8=0;r8<8;r8++){
    int r=warp*8+r8;
    float s=0.f,s2=0.f;
    #pragma unroll
    for(int i=0;i<6;i++){float v=Ys[r*196+lane+32*i]; s+=v; s2+=v*v;}
    #pragma unroll
    for(int o=16;o>0;o>>=1){s+=__shfl_xor_sync(~0u,s,o); s2+=__shfl_xor_sync(~0u,s2,o);}
    float mu=s*(1.f/192.f), rs=rsqrtf(s2*(1.f/192.f)-mu*mu+1e-5f);
    #pragma unroll
    for(int i=0;i<6;i++){int c=lane+32*i;
      float v=(Ys[r*196+c]-mu)*rs*lg[c]+lb[c];
      if(POOL) Ys[r*196+c]=v; else Out[(long)(row0+r)*192+c]=v;
    }
  }
  if(POOL){
    __syncthreads();
    for(int idx=tid; idx<32*192; idx+=TB){int i=idx/192,c=idx%192;
      Out[(long)(row0/2+i)*192+c]=0.5f*(Ys[(2*i)*196+c]+Ys[(2*i+1)*196+c]);}
  }
}

// fingerprint head: z@fp_w^T + b, then L2 normalize per row
__global__ __launch_bounds__(TB,1) void k_fp(const float* __restrict__ X,
    const float* __restrict__ W,const float* __restrict__ bias,float* __restrict__ Out){
  extern __shared__ float sm[];
  float* Xs=sm; float* Wb=Xs+64*196; float* Ys=Wb+2*128*WLD;
  int tid=threadIdx.x,row0=blockIdx.x*64;
  load_tile<192>(Xs,196,X,192,row0,tid);
  __syncthreads();
  float acc[8][4];
  gemm_tile<192,8>(acc,Xs,196,W,Wb,tid);
  int lane=tid&31,warp=tid>>5,wm=warp&3,wn=warp>>2,gid=lane>>2,t4=lane&3;
  #pragma unroll
  for(int nt=0;nt<8;nt++){
    int n=wn*64+nt*8+2*t4;
    #pragma unroll
    for(int e=0;e<4;e++){
      int m=wm*16+gid+(e>>1)*8,nn=n+(e&1);
      Ys[m*132+nn]=acc[nt][e]+bias[nn];
    }
  }
  __syncthreads();
  for(int r8=0;r8<8;r8++){
    int r=warp*8+r8;
    float s2=0.f;
    #pragma unroll
    for(int i=0;i<4;i++){float v=Ys[r*132+lane+32*i]; s2+=v*v;}
    #pragma unroll
    for(int o=16;o>0;o>>=1) s2+=__shfl_xor_sync(~0u,s2,o);
    float sc=1.f/fmaxf(sqrtf(s2),1e-12f);
    #pragma unroll
    for(int i=0;i<4;i++){int c=lane+32*i; Out[(long)(row0+r)*128+c]=Ys[r*132+c]*sc;}
  }
}

// 2x2 attention per sample (warp per sample); qkv row = [q|k|v], head cols h*64..
__global__ __launch_bounds__(TB,1) void k_attn(){
  int lane=threadIdx.x&31,warp=threadIdx.x>>5;
  long s=(long)blockIdx.x*8+warp;
  const float* b0=g_qkv+s*2*576;
  const float* b1=b0+576;
  for(int h=0;h<3;h++){
    int o=h*64;
    float q0a=b0[o+lane],q0b=b0[o+32+lane],q1a=b1[o+lane],q1b=b1[o+32+lane];
    float k0a=b0[o+192+lane],k0b=b0[o+224+lane],k1a=b1[o+192+lane],k1b=b1[o+224+lane];
    float pp=q0a*k0a+q0b*k0b, pt=q0a*k1a+q0b*k1b, tp=q1a*k0a+q1b*k0b, tt=q1a*k1a+q1b*k1b;
    for(int x=16;x>0;x>>=1){pp+=__shfl_xor_sync(~0u,pp,x);pt+=__shfl_xor_sync(~0u,pt,x);
      tp+=__shfl_xor_sync(~0u,tp,x);tt+=__shfl_xor_sync(~0u,tt,x);}
    pp*=0.125f;pt*=0.125f;tp*=0.125f;tt*=0.125f;
    float m0=fmaxf(pp,pt),e0=expf(pp-m0),e1=expf(pt-m0),iv=1.f/(e0+e1);
    float m1=fmaxf(tp,tt),f0=expf(tp-m1),f1=expf(tt-m1),jv=1.f/(f0+f1);
    float a00=e0*iv,a01=e1*iv,a10=f0*jv,a11=f1*jv;
    float v0a=b0[o+384+lane],v0b=b0[o+416+lane],v1a=b1[o+384+lane],v1b=b1[o+416+lane];
    float* c0=g_ctx+s*2*192+o; float* c1=c0+192;
    c0[lane]=a00*v0a+a01*v1a; c0[32+lane]=a00*v0b+a01*v1b;
    c1[lane]=a10*v0a+a11*v1a; c1[32+lane]=a10*v0b+a11*v1b;
  }
}

// classifier logits + sigmoid (warp per sample)
__global__ __launch_bounds__(TB,1) void k_cls2(const float* __restrict__ W,
    const float* __restrict__ bias,float* __restrict__ out,int B){
  int lane=threadIdx.x&31,warp=threadIdx.x>>5;
  long s=(long)blockIdx.x*8+warp;
  const float* h=g_h1+s*192;
  float d0=0.f,d1=0.f,d2=0.f;
  #pragma unroll
  for(int i=0;i<6;i++){int c=lane+32*i; float v=h[c];
    d0+=v*W[c]; d1+=v*W[192+c]; d2+=v*W[384+c];}
  for(int x=16;x>0;x>>=1){d0+=__shfl_xor_sync(~0u,d0,x);d1+=__shfl_xor_sync(~0u,d1,x);d2+=__shfl_xor_sync(~0u,d2,x);}
  if(lane==0){
    out[s]      =1.f/(1.f+expf(-(d0+bias[0])));
    out[B+s]    =1.f/(1.f+expf(-(d1+bias[1])));
    out[2L*B+s] =1.f/(1.f+expf(-(d2+bias[2])));
  }
}

extern "C" void kernel_launch(void* const* d_in,const int* in_sizes,int n_in,void* d_out,int out_size){
  const float* perc=(const float*)d_in[0];
  const float* tech=(const float*)d_in[1];
  const float* Wp=(const float*)d_in[2];  const float* bp=(const float*)d_in[3];
  const float* Wt=(const float*)d_in[4];  const float* bt=(const float*)d_in[5];
  const float* in_w=(const float*)d_in[6];const float* in_b=(const float*)d_in[7];
  const float* ow=(const float*)d_in[8];  const float* ob=(const float*)d_in[9];
  const float* f1w=(const float*)d_in[10];const float* f1b=(const float*)d_in[11];
  const float* f2w=(const float*)d_in[12];const float* f2b=(const float*)d_in[13];
  const float* l1g=(const float*)d_in[14];const float* l1b=(const float*)d_in[15];
  const float* l2g=(const float*)d_in[16];const float* l2b=(const float*)d_in[17];
  const float* c1w=(const float*)d_in[18];const float* c1b=(const float*)d_in[19];
  const float* c2w=(const float*)d_in[20];const float* c2b=(const float*)d_in[21];
  const float* fpw=(const float*)d_in[22];const float* fpb=(const float*)d_in[23];
  int B=in_sizes[0]/192;
  float* out=(float*)d_out;

  float *seq,*qkv,*ctx,*x,*hh,*z,*h1;
  cudaGetSymbolAddress((void**)&seq,g_seq);
  cudaGetSymbolAddress((void**)&qkv,g_qkv);
  cudaGetSymbolAddress((void**)&ctx,g_ctx);
  cudaGetSymbolAddress((void**)&x,  g_x);
  cudaGetSymbolAddress((void**)&hh, g_h);
  cudaGetSymbolAddress((void**)&z,  g_z);
  cudaGetSymbolAddress((void**)&h1, g_h1);

  const int SZG =(64*196+2*192*WLD)*4;
  const int SZL1=SZG+64*196*4;
  const int SZL2=(64*388+2*192*WLD+64*196)*4;
  const int SZF =(64*196+2*128*WLD+64*132)*4;
  cudaFuncSetAttribute(k_gemm<192,12>,      cudaFuncAttributeMaxDynamicSharedMemorySize,SZG);
  cudaFuncSetAttribute(k_ln<192,false>,     cudaFuncAttributeMaxDynamicSharedMemorySize,SZL1);
  cudaFuncSetAttribute(k_ln<384,true>,      cudaFuncAttributeMaxDynamicSharedMemorySize,SZL2);
  cudaFuncSetAttribute(k_fp,                cudaFuncAttributeMaxDynamicSharedMemorySize,SZF);

  int Rs=B/64, R2=2*B/64;
  // 1) projections -> seq (token-interleaved rows)
  k_gemm<192,12><<<Rs,TB,SZG>>>(perc,192,seq,    384,Wp,bp,0);
  k_gemm<192,12><<<Rs,TB,SZG>>>(tech,192,seq+192,384,Wt,bt,0);
  // 2) qkv (N=576 as 3 chunks of 192)
  k_gemm<192,12><<<dim3(R2,3),TB,SZG>>>(seq,192,qkv,576,in_w,in_b,0);
  // 3) attention -> ctx
  k_attn<<<B/8,TB>>>();
  // 4) out-proj + residual + LN1 -> x
  k_ln<192,false><<<R2,TB,SZL1>>>(ctx,seq,ow,ob,l1g,l1b,x);
  // 5) FFN1 relu -> h (N=384 as 2 chunks)
  k_gemm<192,12><<<dim3(R2,2),TB,SZG>>>(x,192,hh,384,f1w,f1b,1);
  // 6) FFN2 + residual + LN2 + token-mean -> z
  k_ln<384,true><<<R2,TB,SZL2>>>(hh,x,f2w,f2b,l2g,l2b,z);
  // 7) cls hidden relu -> h1
  k_gemm<192,12><<<Rs,TB,SZG>>>(z,192,h1,192,c1w,c1b,1);
  // 8) fingerprint + normalize -> out[3B:]
  k_fp<<<Rs,TB,SZF>>>(z,fpw,fpb,out+3L*B);
  // 9) logits + sigmoid -> out[0:3B]
  k_cls2<<<B/8,TB>>>(c2w,c2b,out,B);
}

// round 7
// speedup vs baseline: 1.8776x; 1.8776x over previous
#include <cuda_runtime.h>
#include <cuda_bf16.h>
#define TB 256
typedef unsigned U;

// packed weights (bf16 hi/lo, chunk-transposed) + activation hi/lo planes
__device__ U g_wpk[448512];
__device__ U g_seq[131072*96*2];
__device__ U g_qkv[131072*288*2];
__device__ U g_ctx[131072*96*2];
__device__ U g_x  [131072*96*2];
__device__ U g_h  [131072*192*2];
__device__ U g_z  [65536*96*2];
__device__ U g_h1 [65536*96*2];

__device__ __forceinline__ void split2(float a,float b,U&hw,U&lw){
  __nv_bfloat162 h=__floats2bfloat162_rn(a,b);
  float2 hf=__bfloat1622float2(h);
  __nv_bfloat162 l=__floats2bfloat162_rn(a-hf.x,b-hf.y);
  hw=*(U*)&h; lw=*(U*)&l;
}
__device__ __forceinline__ float2 un2(U hw,U lw){
  float2 a=__bfloat1622float2(*(__nv_bfloat162*)&hw);
  float2 b=__bfloat1622float2(*(__nv_bfloat162*)&lw);
  return make_float2(a.x+b.x,a.y+b.y);
}
__device__ __forceinline__ void mma16(float* d,U a0,U a1,U a2,U a3,U b0,U b1){
  asm volatile("mma.sync.aligned.m16n8k16.row.col.f32.bf16.bf16.f32 {%0,%1,%2,%3},{%4,%5,%6,%7},{%8,%9},{%0,%1,%2,%3};"
    :"+f"(d[0]),"+f"(d[1]),"+f"(d[2]),"+f"(d[3]):"r"(a0),"r"(a1),"r"(a2),"r"(a3),"r"(b0),"r"(b1));}
__device__ __forceinline__ void cpa16(U* dst,const U* src){
  U d=(U)__cvta_generic_to_shared(dst);
  asm volatile("cp.async.cg.shared.global [%0],[%1],16;"::"r"(d),"l"(src));}

// pack weight W[N][K] (row stride ldw) -> dst: [chunk][hi/lo][kpair 0..7][NPAD]
__global__ void k_split(const float* __restrict__ W,int ldw,U* __restrict__ dst,int N,int K,int NPAD){
  int tot=N*(K/2);
  for(int i=blockIdx.x*blockDim.x+threadIdx.x;i<tot;i+=gridDim.x*blockDim.x){
    int n=i/(K/2),p=i%(K/2),c=p>>3,kp=p&7;
    U hw,lw; split2(W[n*ldw+2*p],W[n*ldw+2*p+1],hw,lw);
    U* b=dst+c*(16*NPAD)+kp*NPAD+n;
    b[0]=hw; b[8*NPAD]=lw;
  }
}

template<int KTOT>
__device__ __forceinline__ void load_planes(U* As,const U* Xg,int xs,int row0,int tid){
  constexpr int ALD=KTOT/2+4,RW=KTOT/2;
  for(int u=tid;u<64*(RW/4);u+=TB){
    int r=u/(RW/4),cc=u%(RW/4);
    cpa16(As+r*ALD+cc*4,Xg+(long)(row0+r)*xs+cc*4);
  }
}
__device__ __forceinline__ void load_planes32(U* Ah,U* Al,const float* X,int row0,int tid){
  for(int u=tid;u<64*96;u+=TB){
    int r=u/96,cw=u%96;
    float2 v=*(const float2*)(X+(long)(row0+r)*192+2*cw);
    U hw,lw; split2(v.x,v.y,hw,lw);
    Ah[r*100+cw]=hw; Al[r*100+cw]=lw;
  }
}

// acc[NT][4] += A(64xKTOT, hi/lo planes in smem) @ W^T (packed global, streamed)
template<int KTOT,int NT>
__device__ __forceinline__ void gemm_bf(float (*acc)[4],const U* Ah,const U* Al,
    const U* __restrict__ Wg,U* Wb,int tid){
  constexpr int NPAD=NT*16+8,CW=16*NPAD,NC=KTOT/16,ALD=KTOT/2+4;
  int lane=tid&31,warp=tid>>5,wm=warp&3,wn=warp>>2,gid=lane>>2,t4=lane&3;
  #pragma unroll
  for(int i=0;i<NT;i++){acc[i][0]=0.f;acc[i][1]=0.f;acc[i][2]=0.f;acc[i][3]=0.f;}
  for(int u=tid;u<CW/4;u+=TB) cpa16(Wb+4*u,Wg+4*u);
  asm volatile("cp.async.commit_group;");
  for(int c=0;c<NC;c++){
    U* cur=Wb+(c&1)*CW; U* nxt=Wb+((c+1)&1)*CW;
    if(c+1<NC){
      const U* s=Wg+(c+1)*CW;
      for(int u=tid;u<CW/4;u+=TB) cpa16(nxt+4*u,s+4*u);
      asm volatile("cp.async.commit_group;");
      asm volatile("cp.async.wait_group 1;");
    } else asm volatile("cp.async.wait_group 0;");
    __syncthreads();
    int r0=(wm*16+gid)*ALD+c*8+t4;
    U ah0=Ah[r0],ah1=Ah[r0+8*ALD],ah2=Ah[r0+4],ah3=Ah[r0+8*ALD+4];
    U al0=Al[r0],al1=Al[r0+8*ALD],al2=Al[r0+4],al3=Al[r0+8*ALD+4];
    const U* wh=cur; const U* wl=cur+8*NPAD;
    #pragma unroll
    for(int nt=0;nt<NT;nt++){
      int n=wn*(NT*8)+nt*8+gid;
      U bh0=wh[t4*NPAD+n],bh1=wh[(t4+4)*NPAD+n];
      U bl0=wl[t4*NPAD+n],bl1=wl[(t4+4)*NPAD+n];
      mma16(acc[nt],ah0,ah1,ah2,ah3,bh0,bh1);
      mma16(acc[nt],al0,al1,al2,al3,bh0,bh1);
      mma16(acc[nt],ah0,ah1,ah2,ah3,bl0,bl1);
    }
    __syncthreads();
  }
}

// generic GEMM: Y(hi/lo planes) = (relu?)(X @ W^T + b); n-chunks of 192 via blockIdx.y
template<int SRC32>
__global__ __launch_bounds__(TB,2) void k_gemm192(const float* X32,const U* Xh,const U* Xl,int xs,
    U* Yh,U* Yl,int ys,const U* __restrict__ Wpk,int wsz,const float* __restrict__ bias,int relu){
  extern __shared__ U sm[];
  U* Ah=sm; U* Al=sm+6400; U* Wb=sm+12800;
  int tid=threadIdx.x,row0=blockIdx.x*64,n0=blockIdx.y*192,n0w=n0>>1;
  if(SRC32) load_planes32(Ah,Al,X32,row0,tid);
  else { load_planes<192>(Ah,Xh,xs,row0,tid); load_planes<192>(Al,Xl,xs,row0,tid); }
  asm volatile("cp.async.commit_group;");
  float acc[12][4];
  gemm_bf<192,12>(acc,Ah,Al,Wpk+(long)blockIdx.y*wsz,Wb,tid);
  int lane=tid&31,warp=tid>>5,wm=warp&3,wn=warp>>2,gid=lane>>2,t4=lane&3;
  #pragma unroll
  for(int nt=0;nt<12;nt++){
    int n=wn*96+nt*8+2*t4,m=wm*16+gid;
    float b0=bias[n0+n],b1=bias[n0+n+1];
    float v0=acc[nt][0]+b0,v1=acc[nt][1]+b1,v2=acc[nt][2]+b0,v3=acc[nt][3]+b1;
    if(relu){v0=fmaxf(v0,0.f);v1=fmaxf(v1,0.f);v2=fmaxf(v2,0.f);v3=fmaxf(v3,0.f);}
    U hw,lw; long o=(long)(row0+m)*ys+n0w+(n>>1);
    split2(v0,v1,hw,lw); Yh[o]=hw; Yl[o]=lw;
    o=(long)(row0+m+8)*ys+n0w+(n>>1);
    split2(v2,v3,hw,lw); Yh[o]=hw; Yl[o]=lw;
  }
}

// GEMM(192 out) + residual + LayerNorm (+ optional token-pair mean pooling)
template<int KTOT,int POOL>
__global__ __launch_bounds__(TB) void k_ln(const U* Xh,const U* Xl,int xs,
    const U* Rh,const U* Rl,const U* __restrict__ Wpk,const float* __restrict__ bias,
    const float* __restrict__ lg,const float* __restrict__ lb,U* Oh,U* Ol){
  extern __shared__ U sm[];
  constexpr int ALD=KTOT/2+4;
  U* Ah=sm; U* Al=sm+64*ALD; U* Wb=sm+128*ALD;
  int tid=threadIdx.x,row0=blockIdx.x*64;
  load_planes<KTOT>(Ah,Xh,xs,row0,tid);
  load_planes<KTOT>(Al,Xl,xs,row0,tid);
  asm volatile("cp.async.commit_group;");
  float acc[12][4];
  gemm_bf<KTOT,12>(acc,Ah,Al,Wpk,Wb,tid);
  float* Ys=(float*)sm;  // reuse A planes (gemm done)
  int lane=tid&31,warp=tid>>5,wm=warp&3,wn=warp>>2,gid=lane>>2,t4=lane&3;
  #pragma unroll
  for(int nt=0;nt<12;nt++){
    int n=wn*96+nt*8+2*t4,m=wm*16+gid;
    float b0=bias[n],b1=bias[n+1];
    long ro=(long)(row0+m)*96+(n>>1);
    float2 r=un2(Rh[ro],Rl[ro]);
    Ys[m*196+n]=acc[nt][0]+b0+r.x; Ys[m*196+n+1]=acc[nt][1]+b1+r.y;
    ro=(long)(row0+m+8)*96+(n>>1);
    r=un2(Rh[ro],Rl[ro]);
    Ys[(m+8)*196+n]=acc[nt][2]+b0+r.x; Ys[(m+8)*196+n+1]=acc[nt][3]+b1+r.y;
  }
  __syncthreads();
  for(int r8=0;r8<8;r8++){
    int r=warp*8+r8;
    float s=0.f,s2=0.f;
    #pragma unroll
    for(int i=0;i<6;i++){float v=Ys[r*196+lane+32*i]; s+=v; s2+=v*v;}
    #pragma unroll
    for(int o=16;o>0;o>>=1){s+=__shfl_xor_sync(~0u,s,o); s2+=__shfl_xor_sync(~0u,s2,o);}
    float mu=s*(1.f/192.f),rs=rsqrtf(s2*(1.f/192.f)-mu*mu+1e-5f);
    #pragma unroll
    for(int i=0;i<3;i++){
      int w=lane+32*i;
      float v0=(Ys[r*196+2*w]-mu)*rs*lg[2*w]+lb[2*w];
      float v1=(Ys[r*196+2*w+1]-mu)*rs*lg[2*w+1]+lb[2*w+1];
      if(POOL){Ys[r*196+2*w]=v0; Ys[r*196+2*w+1]=v1;}
      else{U hw,lw; split2(v0,v1,hw,lw); long o=(long)(row0+r)*96+w; Oh[o]=hw; Ol[o]=lw;}
    }
  }
  if(POOL){
    __syncthreads();
    for(int idx=tid;idx<32*96;idx+=TB){
      int i=idx/96,w=idx%96;
      float v0=0.5f*(Ys[(2*i)*196+2*w]+Ys[(2*i+1)*196+2*w]);
      float v1=0.5f*(Ys[(2*i)*196+2*w+1]+Ys[(2*i+1)*196+2*w+1]);
      U hw,lw; split2(v0,v1,hw,lw);
      long o=(long)(row0/2+i)*96+w; Oh[o]=hw; Ol[o]=lw;
    }
  }
}

// fingerprint head: z @ fp_w^T + b, L2-normalize
__global__ __launch_bounds__(TB) void k_fp(const U* Xh,const U* Xl,
    const U* __restrict__ Wpk,const float* __restrict__ bias,float* __restrict__ Out){
  extern __shared__ U sm[];
  U* Ah=sm; U* Al=sm+6400; U* Wb=sm+12800;
  int tid=threadIdx.x,row0=blockIdx.x*64;
  load_planes<192>(Ah,Xh,96,row0,tid);
  load_planes<192>(Al,Xl,96,row0,tid);
  asm volatile("cp.async.commit_group;");
  float acc[8][4];
  gemm_bf<192,8>(acc,Ah,Al,Wpk,Wb,tid);
  float* Ys=(float*)sm;
  int lane=tid&31,warp=tid>>5,wm=warp&3,wn=warp>>2,gid=lane>>2,t4=lane&3;
  #pragma unroll
  for(int nt=0;nt<8;nt++){
    int n=wn*64+nt*8+2*t4,m=wm*16+gid;
    Ys[m*132+n]=acc[nt][0]+bias[n];   Ys[m*132+n+1]=acc[nt][1]+bias[n+1];
    Ys[(m+8)*132+n]=acc[nt][2]+bias[n]; Ys[(m+8)*132+n+1]=acc[nt][3]+bias[n+1];
  }
  __syncthreads();
  for(int r8=0;r8<8;r8++){
    int r=warp*8+r8;
    float s2=0.f;
    #pragma unroll
    for(int i=0;i<4;i++){float v=Ys[r*132+lane+32*i]; s2+=v*v;}
    #pragma unroll
    for(int o=16;o>0;o>>=1) s2+=__shfl_xor_sync(~0u,s2,o);
    float sc=1.f/fmaxf(sqrtf(s2),1e-12f);
    #pragma unroll
    for(int i=0;i<4;i++){int c=lane+32*i; Out[(long)(row0+r)*128+c]=Ys[r*132+c]*sc;}
  }
}

// 2x2 attention per sample (warp per sample), word-packed
__global__ __launch_bounds__(TB) void k_attn(){
  int lane=threadIdx.x&31,warp=threadIdx.x>>5;
  long s=(long)blockIdx.x*8+warp;
  const U* H=g_qkv; const U* L=g_qkv+131072*288;
  U* CH=g_ctx; U* CL=g_ctx+131072*96;
  long r0=s*2*288,r1=r0+288;
  for(int h=0;h<3;h++){
    int o=h*32+lane;
    float2 q0=un2(H[r0+o],L[r0+o]),q1=un2(H[r1+o],L[r1+o]);
    float2 k0=un2(H[r0+96+o],L[r0+96+o]),k1=un2(H[r1+96+o],L[r1+96+o]);
    float pp=q0.x*k0.x+q0.y*k0.y,pt=q0.x*k1.x+q0.y*k1.y;
    float tp=q1.x*k0.x+q1.y*k0.y,tt=q1.x*k1.x+q1.y*k1.y;
    #pragma unroll
    for(int x=16;x>0;x>>=1){pp+=__shfl_xor_sync(~0u,pp,x);pt+=__shfl_xor_sync(~0u,pt,x);
      tp+=__shfl_xor_sync(~0u,tp,x);tt+=__shfl_xor_sync(~0u,tt,x);}
    pp*=0.125f;pt*=0.125f;tp*=0.125f;tt*=0.125f;
    float m0=fmaxf(pp,pt),e0=expf(pp-m0),e1=expf(pt-m0),iv=1.f/(e0+e1);
    float m1=fmaxf(tp,tt),f0=expf(tp-m1),f1=expf(tt-m1),jv=1.f/(f0+f1);
    float a00=e0*iv,a01=e1*iv,a10=f0*jv,a11=f1*jv;
    float2 v0=un2(H[r0+192+o],L[r0+192+o]),v1=un2(H[r1+192+o],L[r1+192+o]);
    U hw,lw;
    long c0=s*2*96+h*32+lane,c1=c0+96;
    split2(a00*v0.x+a01*v1.x,a00*v0.y+a01*v1.y,hw,lw); CH[c0]=hw; CL[c0]=lw;
    split2(a10*v0.x+a11*v1.x,a10*v0.y+a11*v1.y,hw,lw); CH[c1]=hw; CL[c1]=lw;
  }
}

// classifier logits + sigmoid (warp per sample)
__global__ __launch_bounds__(TB) void k_cls2(const float* __restrict__ W,
    const float* __restrict__ bias,float* __restrict__ out,int B){
  int lane=threadIdx.x&31,warp=threadIdx.x>>5;
  long s=(long)blockIdx.x*8+warp;
  const U* H=g_h1; const U* L=g_h1+65536*96;
  float d0=0.f,d1=0.f,d2=0.f;
  #pragma unroll
  for(int i=0;i<3;i++){
    int w=lane+32*i;
    float2 v=un2(H[s*96+w],L[s*96+w]);
    d0+=v.x*W[2*w]+v.y*W[2*w+1];
    d1+=v.x*W[192+2*w]+v.y*W[192+2*w+1];
    d2+=v.x*W[384+2*w]+v.y*W[384+2*w+1];
  }
  #pragma unroll
  for(int x=16;x>0;x>>=1){d0+=__shfl_xor_sync(~0u,d0,x);d1+=__shfl_xor_sync(~0u,d1,x);d2+=__shfl_xor_sync(~0u,d2,x);}
  if(lane==0){
    out[s]     =1.f/(1.f+expf(-(d0+bias[0])));
    out[B+s]   =1.f/(1.f+expf(-(d1+bias[1])));
    out[2L*B+s]=1.f/(1.f+expf(-(d2+bias[2])));
  }
}

extern "C" void kernel_launch(void* const* d_in,const int* in_sizes,int n_in,void* d_out,int out_size){
  const float* perc=(const float*)d_in[0];
  const float* tech=(const float*)d_in[1];
  const float* Wp=(const float*)d_in[2];  const float* bp=(const float*)d_in[3];
  const float* Wt=(const float*)d_in[4];  const float* bt=(const float*)d_in[5];
  const float* in_w=(const float*)d_in[6];const float* in_b=(const float*)d_in[7];
  const float* ow=(const float*)d_in[8];  const float* ob=(const float*)d_in[9];
  const float* f1w=(const float*)d_in[10];const float* f1b=(const float*)d_in[11];
  const float* f2w=(const float*)d_in[12];const float* f2b=(const float*)d_in[13];
  const float* l1g=(const float*)d_in[14];const float* l1b=(const float*)d_in[15];
  const float* l2g=(const float*)d_in[16];const float* l2b=(const float*)d_in[17];
  const float* c1w=(const float*)d_in[18];const float* c1b=(const float*)d_in[19];
  const float* c2w=(const float*)d_in[20];const float* c2b=(const float*)d_in[21];
  const float* fpw=(const float*)d_in[22];const float* fpb=(const float*)d_in[23];
  int B=in_sizes[0]/192;
  float* out=(float*)d_out;

  U *wpk,*seq,*qkv,*ctx,*x,*hh,*z,*h1;
  cudaGetSymbolAddress((void**)&wpk,g_wpk);
  cudaGetSymbolAddress((void**)&seq,g_seq);
  cudaGetSymbolAddress((void**)&qkv,g_qkv);
  cudaGetSymbolAddress((void**)&ctx,g_ctx);
  cudaGetSymbolAddress((void**)&x,g_x);
  cudaGetSymbolAddress((void**)&hh,g_h);
  cudaGetSymbolAddress((void**)&z,g_z);
  cudaGetSymbolAddress((void**)&h1,g_h1);
  U *seqL=seq+131072*96,*qkvL=qkv+131072*288,*ctxL=ctx+131072*96;
  U *xL=x+131072*96,*hhL=hh+131072*192,*zL=z+65536*96,*h1L=h1+65536*96;

  const int SZG=76800,SZL2=125952,SZF=68608;
  cudaFuncSetAttribute(k_gemm192<0>,cudaFuncAttributeMaxDynamicSharedMemorySize,SZG);
  cudaFuncSetAttribute(k_gemm192<1>,cudaFuncAttributeMaxDynamicSharedMemorySize,SZG);
  cudaFuncSetAttribute(k_ln<192,0>, cudaFuncAttributeMaxDynamicSharedMemorySize,SZG);
  cudaFuncSetAttribute(k_ln<384,1>, cudaFuncAttributeMaxDynamicSharedMemorySize,SZL2);
  cudaFuncSetAttribute(k_fp,        cudaFuncAttributeMaxDynamicSharedMemorySize,SZF);

  // pre-split all weights into packed hi/lo layout
  const int S192=38400,S384=76800;
  k_split<<<72,TB>>>(Wp,192,wpk+0,192,192,200);
  k_split<<<72,TB>>>(Wt,192,wpk+38400,192,192,200);
  for(int j=0;j<3;j++) k_split<<<72,TB>>>(in_w+j*192*192,192,wpk+76800+j*S192,192,192,200);
  k_split<<<72,TB>>>(ow,192,wpk+192000,192,192,200);
  for(int j=0;j<2;j++) k_split<<<72,TB>>>(f1w+j*192*192,192,wpk+230400+j*S192,192,192,200);
  k_split<<<144,TB>>>(f2w,384,wpk+307200,192,384,200);
  k_split<<<72,TB>>>(c1w,192,wpk+384000,192,192,200);
  k_split<<<48,TB>>>(fpw,192,wpk+422400,128,192,136);
  (void)S384;

  int Rs=B/64,R2=2*B/64;
  // 1) projections -> seq planes (token-interleaved rows, stride 192 words)
  k_gemm192<1><<<Rs,TB,SZG>>>(perc,0,0,0,seq,seqL,192,wpk+0,S192,bp,0);
  k_gemm192<1><<<Rs,TB,SZG>>>(tech,0,0,0,seq+96,seqL+96,192,wpk+38400,S192,bt,0);
  // 2) qkv
  k_gemm192<0><<<dim3(R2,3),TB,SZG>>>(0,seq,seqL,96,qkv,qkvL,288,wpk+76800,S192,in_b,0);
  // 3) attention -> ctx
  k_attn<<<B/8,TB>>>();
  // 4) out-proj + residual + LN1 -> x
  k_ln<192,0><<<R2,TB,SZG>>>(ctx,ctxL,96,seq,seqL,wpk+192000,ob,l1g,l1b,x,xL);
  // 5) FFN1 relu -> h
  k_gemm192<0><<<dim3(R2,2),TB,SZG>>>(0,x,xL,96,hh,hhL,192,wpk+230400,S192,f1b,1);
  // 6) FFN2 + residual + LN2 + pool -> z
  k_ln<384,1><<<R2,TB,SZL2>>>(hh,hhL,192,x,xL,wpk+307200,f2b,l2g,l2b,z,zL);
  // 7) cls hidden relu -> h1
  k_gemm192<0><<<dim3(Rs,1),TB,SZG>>>(0,z,zL,96,h1,h1L,96,wpk+384000,S192,c1b,1);
  // 8) fingerprint + normalize -> out[3B:]
  k_fp<<<Rs,TB,SZF>>>(z,zL,wpk+422400,fpb,out+3L*B);
  // 9) logits + sigmoid -> out[0:3B]
  k_cls2<<<B/8,TB>>>(c2w,c2b,out,B);
}